// round 14
// baseline (speedup 1.0000x reference)
#include <cuda_runtime.h>
#include <cuda_fp16.h>
#include <math.h>
#include <stdint.h>

#define TDIM 512
#define TOUT 1024
#define TBATCH 65536

// W in fp16, pre-transposed into per-(stage, group) 4KB blocks:
// block id b = (s*8 + g), s = c*8+kt (c: 256-row chunk, kt: 64-wide k-tile),
// g: 32-row N slice. Within block: elem (n',k=u*8+j) at (u*32+n')*8+j.
__device__ __half g_W16[TOUT * TDIM];
__device__ float  g_invf[TDIM];

__global__ void prep_kernel(const float* __restrict__ W) {
    int idx = blockIdx.x * blockDim.x + threadIdx.x;
    if (idx < TOUT * TDIM) {
        int b      = idx >> 11;            // 4KB block = 2048 elems
        int within = idx & 2047;
        int u  = within >> 8;              // k-unit 0..7
        int np = (within >> 3) & 31;       // local row 0..31
        int j  = within & 7;
        int g  = b & 7;
        int kt = (b >> 3) & 7;
        int c  = b >> 6;
        int row = c * 256 + g * 32 + np;
        int col = kt * 64 + u * 8 + j;
        g_W16[idx] = __float2half_rn(W[row * 512 + col]);
    }
    if (idx < TDIM) {
        float a  = (2.0f * (float)idx) / 512.0f;
        float xf = __fmul_rn(a, 9.210340371976184f);
        g_invf[idx] = (float)exp(-(double)xf);
    }
}

// Accurate sin/cos for x in [0, ~1024] rad. odd=0 -> sin, odd=1 -> cos.
__device__ __forceinline__ float sincos_sel(float x, int odd) {
    float j  = __fmaf_rn(x, 0.63661977236758134f, 12582912.0f);
    int   qi = __float_as_int(j);
    float jf = __fadd_rn(j, -12582912.0f);
    float r  = __fmaf_rn(jf, -1.57079601e+00f, x);
    r        = __fmaf_rn(jf, -3.13916473e-07f, r);
    r        = __fmaf_rn(jf, -5.39030253e-15f, r);
    float r2 = __fmul_rn(r, r);
    float ps = __fmaf_rn(2.75573192e-6f, r2, -1.98412698e-4f);
    ps = __fmaf_rn(ps, r2, 8.33333333e-3f);
    ps = __fmaf_rn(ps, r2, -1.66666667e-1f);
    float sp = __fmaf_rn(ps * r2, r, r);
    float pc = __fmaf_rn(2.48015873e-5f, r2, -1.38888889e-3f);
    pc = __fmaf_rn(pc, r2, 4.16666667e-2f);
    pc = __fmaf_rn(pc, r2, -5.0e-1f);
    float cp = __fmaf_rn(pc, r2, 1.0f);
    int qq = qi + odd;
    float v = (qq & 1) ? cp : sp;
    return (qq & 2) ? -v : v;
}

#define CP_ASYNC16(dst, src) \
    asm volatile("cp.async.cg.shared.global [%0], [%1], 16;" :: "r"(dst), "l"(src))
#define CP_COMMIT()  asm volatile("cp.async.commit_group;")
#define CP_WAIT1()   asm volatile("cp.async.wait_group 1;")
#define CP_WAIT0()   asm volatile("cp.async.wait_group 0;")
#define GBAR64(id)   asm volatile("bar.sync %0, 64;" :: "r"(id) : "memory")

// --------------------------- SMEM layout ------------------------------------
// A: 64 k-planes of [128 rows x 16B], plane stride 2080 (32B skew) = 133120 B
// B: 8 group-private rings, 3 stages x 4KB each (32 n x 64 k fp16) = 98304 B
#define A_OFF     0
#define A_PLANE   2080
#define B_OFF     133120
#define B_SLICE   4096
#define SMEM_TOTAL 231424

__device__ __forceinline__ void ldmat4(uint32_t addr, uint32_t* r) {
    asm volatile("ldmatrix.sync.aligned.m8n8.x4.shared.b16 {%0,%1,%2,%3}, [%4];"
                 : "=r"(r[0]), "=r"(r[1]), "=r"(r[2]), "=r"(r[3]) : "r"(addr));
}

// 512 threads, 16 warps = 2M x 8N; warp tile 64M x 32N; acc = 64 regs.
// Grid (512, 2): blockIdx.x = M tile, blockIdx.y = N half (512 cols each).
__global__ void __launch_bounds__(512, 1) temb_main(
    const float* __restrict__ T,
    const float* __restrict__ bias,
    float* __restrict__ out)
{
    extern __shared__ char smem[];
    const int tid = threadIdx.x;
    const int mbase = blockIdx.x * 128;
    const int nhalf = blockIdx.y;        // 0 or 1: owns 16 of the 32 W stages
    uint32_t sbase;
    asm("{ .reg .u64 t; cvta.to.shared.u64 t, %1; cvt.u32.u64 %0, t; }"
        : "=r"(sbase) : "l"(smem));

    const int w      = tid >> 5;
    const int lane   = tid & 31;
    const int g      = w >> 1;          // N-slice group (0..7), 2 warps / 64 thr
    const int mw     = (w & 1) * 64;    // warp M offset (0 or 64)
    const int wg_tid = tid & 63;

    // Group-private ring; identity cp.async: 4KB slice, 4 x 16B per thread.
    const uint32_t ring = sbase + B_OFF + (uint32_t)(g * 3) * B_SLICE;
    uint32_t cp_off[4];
    #pragma unroll
    for (int i = 0; i < 4; i++) cp_off[i] = (uint32_t)(wg_tid * 16 + i * 1024);
    const char* wsrc = (const char*)g_W16;
    const int   sg0  = nhalf * 16;      // first global stage for this N half

    // ---- Prologue: start this group's pipeline for stages 0,1 ----
    #pragma unroll
    for (int s = 0; s < 2; s++) {
        const char* sb = wsrc + (size_t)((sg0 + s) * 8 + g) * 4096;
        uint32_t db = ring + (uint32_t)(s % 3) * B_SLICE;
        #pragma unroll
        for (int i = 0; i < 4; i++)
            CP_ASYNC16(db + cp_off[i], sb + cp_off[i]);
        CP_COMMIT();
    }

    // ---- Phase 1: embedding -> A smem (k-plane layout), overlaps cp.async ----
    for (int p = tid; p < 128 * 256; p += 512) {
        int row = p >> 8;
        int c2  = (p & 255) * 2;
        float t  = __ldg(&T[mbase + row]);
        float e0 = sincos_sel(__fmul_rn(t, g_invf[c2]), 0);
        float e1 = sincos_sel(__fmul_rn(t, g_invf[c2 + 1]), 1);
        __half2 h = __floats2half2_rn(e0, e1);
        int u = c2 >> 3;
        *(__half2*)(smem + A_OFF + u * A_PLANE + row * 16 + ((c2 & 7) << 1)) = h;
    }
    __syncthreads();    // A ready; ONLY CTA-wide barrier. Groups free-run after.

    // ---- ldmatrix lane geometry ----
    const int arow0 = mw + ((lane >> 3) & 1) * 8 + (lane & 7);
    const int a_c8  = lane >> 4;
    const int bn0   = (lane & 7) + ((lane >> 4) << 3);  // local n 0..15
    const int b_k8  = (lane >> 3) & 1;

    const uint32_t a_base0 = sbase + A_OFF + (uint32_t)a_c8 * A_PLANE
                           + (uint32_t)arow0 * 16u;
    const uint32_t b_lane  = (uint32_t)b_k8 * 512u + (uint32_t)bn0 * 16u;

    float acc[4][4][4];   // [m16-tile][n8-tile][quad] = 64 regs

    for (int s = 0; s < 16; s++) {
        const int kt = s & 7, nb = s >> 3, buf = s % 3;

        if (kt == 0) {
            #pragma unroll
            for (int mt = 0; mt < 4; mt++)
                #pragma unroll
                for (int nt = 0; nt < 4; nt++) {
                    acc[mt][nt][0] = 0.f; acc[mt][nt][1] = 0.f;
                    acc[mt][nt][2] = 0.f; acc[mt][nt][3] = 0.f;
                }
        }

        // Group-local: own cp.asyncs done (leave newest in flight), publish
        // slice within the 64-thread group only.
        if (s == 15) { CP_WAIT0(); } else { CP_WAIT1(); }
        GBAR64(g + 1);

        // issue stage s+2 into buffer (s+2)%3 (free: last read at iter s-1)
        if (s + 2 < 16) {
            int s2 = s + 2;
            const char* sb = wsrc + (size_t)((sg0 + s2) * 8 + g) * 4096;
            uint32_t db = ring + (uint32_t)(s2 % 3) * B_SLICE;
            #pragma unroll
            for (int i = 0; i < 4; i++)
                CP_ASYNC16(db + cp_off[i], sb + cp_off[i]);
            CP_COMMIT();
        }

        // ---- MMA over this 64-wide k-tile ----
        const uint32_t a_kt = a_base0 + (uint32_t)(kt * 8) * A_PLANE;
        const uint32_t b_st = ring + (uint32_t)buf * B_SLICE + b_lane;
        #pragma unroll
        for (int kk = 0; kk < 4; kk++) {
            uint32_t a[4][4];
            const uint32_t a_kk = a_kt + (uint32_t)(kk * 2) * A_PLANE;
            #pragma unroll
            for (int mt = 0; mt < 4; mt++)
                ldmat4(a_kk + (uint32_t)mt * 256u, a[mt]);   // +16 rows * 16B
            const uint32_t b_kk = b_st + (uint32_t)kk * 1024u;
            #pragma unroll
            for (int j = 0; j < 2; j++) {
                uint32_t b[4];
                ldmat4(b_kk + (uint32_t)j * 256u, b);        // +16 local n rows
                #pragma unroll
                for (int mt = 0; mt < 4; mt++) {
                    asm volatile(
                        "mma.sync.aligned.m16n8k16.row.col.f32.f16.f16.f32 "
                        "{%0,%1,%2,%3}, {%4,%5,%6,%7}, {%8,%9}, {%0,%1,%2,%3};"
                        : "+f"(acc[mt][2*j][0]), "+f"(acc[mt][2*j][1]),
                          "+f"(acc[mt][2*j][2]), "+f"(acc[mt][2*j][3])
                        : "r"(a[mt][0]), "r"(a[mt][1]), "r"(a[mt][2]), "r"(a[mt][3]),
                          "r"(b[0]), "r"(b[1]));
                    asm volatile(
                        "mma.sync.aligned.m16n8k16.row.col.f32.f16.f16.f32 "
                        "{%0,%1,%2,%3}, {%4,%5,%6,%7}, {%8,%9}, {%0,%1,%2,%3};"
                        : "+f"(acc[mt][2*j+1][0]), "+f"(acc[mt][2*j+1][1]),
                          "+f"(acc[mt][2*j+1][2]), "+f"(acc[mt][2*j+1][3])
                        : "r"(a[mt][0]), "r"(a[mt][1]), "r"(a[mt][2]), "r"(a[mt][3]),
                          "r"(b[2]), "r"(b[3]));
                }
            }
        }

        // ---- Epilogue for finished 256-col chunk ----
        if (kt == 7) {
            const int nchunk = (nhalf * 2 + nb) * 256 + g * 32;
            #pragma unroll
            for (int mt = 0; mt < 4; mt++) {
                int row = mbase + mw + mt * 16 + (lane >> 2);
                #pragma unroll
                for (int nt = 0; nt < 4; nt++) {
                    int col = nchunk + nt * 8 + (lane & 3) * 2;
                    float2 bv = *(const float2*)(bias + col);
                    float v0 = acc[mt][nt][0] + bv.x;
                    float v1 = acc[mt][nt][1] + bv.y;
                    float v2 = acc[mt][nt][2] + bv.x;
                    float v3 = acc[mt][nt][3] + bv.y;
                    v0 = v0 / (1.0f + __expf(-v0));
                    v1 = v1 / (1.0f + __expf(-v1));
                    v2 = v2 / (1.0f + __expf(-v2));
                    v3 = v3 / (1.0f + __expf(-v3));
                    *(float2*)(out + (size_t)row * 1024 + col)       = make_float2(v0, v1);
                    *(float2*)(out + (size_t)(row + 8) * 1024 + col) = make_float2(v2, v3);
                }
            }
        }
    }
}

// ---------------------------------------------------------------------------
extern "C" void kernel_launch(void* const* d_in, const int* in_sizes, int n_in,
                              void* d_out, int out_size) {
    const float* T = (const float*)d_in[0];
    const float* W = (const float*)d_in[1];
    const float* b = (const float*)d_in[2];
    float* out = (float*)d_out;

    prep_kernel<<<(TOUT * TDIM + 255) / 256, 256>>>(W);

    cudaFuncSetAttribute(temb_main, cudaFuncAttributeMaxDynamicSharedMemorySize, SMEM_TOTAL);
    dim3 grid(TBATCH / 128, 2);
    temb_main<<<grid, 512, SMEM_TOTAL>>>(T, b, out);
}

// round 15
// speedup vs baseline: 1.0433x; 1.0433x over previous
#include <cuda_runtime.h>
#include <cuda_fp16.h>
#include <math.h>
#include <stdint.h>

#define TDIM 512
#define TOUT 1024
#define TBATCH 65536

// W in fp16, pre-arranged in EXACT mma.sync B-fragment order so the mainloop
// loads fragments with coalesced LDG.128 (no smem, no cp.async, no barriers).
// Block (c,g) = (256-col chunk, 32-row N slice): 32KB. Within: chunk
// q = kt*8 + kk*2 + j (k16 step kkg=kt*4+kk, n16 half j), 512B: lane*16B.
// Lane l, reg i (e>>1) holds the elements ldmatrix would have delivered.
__device__ __half g_W16[TOUT * TDIM];
__device__ float  g_invf[TDIM];

__global__ void prep_kernel(const float* __restrict__ W) {
    int idx = blockIdx.x * blockDim.x + threadIdx.x;
    if (idx < TOUT * TDIM) {
        int blk    = idx >> 14;            // 32KB block = 16384 elems
        int within = idx & 16383;
        int c = blk >> 3, g = blk & 7;
        int q    = within >> 8;            // 0..63
        int lane = (within >> 3) & 31;
        int e    = within & 7;             // fp16 within lane's 16B
        int kt = q >> 3, kk = (q >> 1) & 3, j = q & 1;
        int i  = e >> 1;                   // fragment reg 0..3
        // ldmatrix distribution rule: lane gets bytes 4*(lane&3) of the row
        // addressed by src_lane = 8*i + (lane>>2).
        int src  = 8 * i + (lane >> 2);
        int u    = kk * 2 + ((src >> 3) & 1);                    // k-unit
        int np   = (src & 7) + ((src >> 4) << 3) + j * 16;       // local n
        int j2   = (lane & 3) * 2 + (e & 1);                     // k within unit
        int row  = c * 256 + g * 32 + np;
        int col  = kt * 64 + u * 8 + j2;
        g_W16[idx] = __float2half_rn(W[row * 512 + col]);
    }
    if (idx < TDIM) {
        float a  = (2.0f * (float)idx) / 512.0f;
        float xf = __fmul_rn(a, 9.210340371976184f);
        g_invf[idx] = (float)exp(-(double)xf);
    }
}

// Accurate sin/cos for x in [0, ~1024] rad. odd=0 -> sin, odd=1 -> cos.
__device__ __forceinline__ float sincos_sel(float x, int odd) {
    float j  = __fmaf_rn(x, 0.63661977236758134f, 12582912.0f);
    int   qi = __float_as_int(j);
    float jf = __fadd_rn(j, -12582912.0f);
    float r  = __fmaf_rn(jf, -1.57079601e+00f, x);
    r        = __fmaf_rn(jf, -3.13916473e-07f, r);
    r        = __fmaf_rn(jf, -5.39030253e-15f, r);
    float r2 = __fmul_rn(r, r);
    float ps = __fmaf_rn(2.75573192e-6f, r2, -1.98412698e-4f);
    ps = __fmaf_rn(ps, r2, 8.33333333e-3f);
    ps = __fmaf_rn(ps, r2, -1.66666667e-1f);
    float sp = __fmaf_rn(ps * r2, r, r);
    float pc = __fmaf_rn(2.48015873e-5f, r2, -1.38888889e-3f);
    pc = __fmaf_rn(pc, r2, 4.16666667e-2f);
    pc = __fmaf_rn(pc, r2, -5.0e-1f);
    float cp = __fmaf_rn(pc, r2, 1.0f);
    int qq = qi + odd;
    float v = (qq & 1) ? cp : sp;
    return (qq & 2) ? -v : v;
}

// --------------------------- SMEM layout ------------------------------------
// A only: 64 k-planes of [128 rows x 16B], plane stride 2080 (32B skew).
#define A_OFF     0
#define A_PLANE   2080
#define SMEM_TOTAL 133120

__device__ __forceinline__ void ldmat4(uint32_t addr, uint32_t* r) {
    asm volatile("ldmatrix.sync.aligned.m8n8.x4.shared.b16 {%0,%1,%2,%3}, [%4];"
                 : "=r"(r[0]), "=r"(r[1]), "=r"(r[2]), "=r"(r[3]) : "r"(addr));
}

// 512 threads, 16 warps = 2M x 8N; warp tile 64M x 32N; acc = 64 regs.
__global__ void __launch_bounds__(512, 1) temb_main(
    const float* __restrict__ T,
    const float* __restrict__ bias,
    float* __restrict__ out)
{
    extern __shared__ char smem[];
    const int tid = threadIdx.x;
    const int mbase = blockIdx.x * 128;
    uint32_t sbase;
    asm("{ .reg .u64 t; cvta.to.shared.u64 t, %1; cvt.u32.u64 %0, t; }"
        : "=r"(sbase) : "l"(smem));

    const int w    = tid >> 5;
    const int lane = tid & 31;
    const int g    = w >> 1;            // N-slice group (0..7)
    const int mw   = (w & 1) * 64;      // warp M offset (0 or 64)

    // ---- Phase 1: embedding -> A smem (k-plane layout) ----
    for (int p = tid; p < 128 * 256; p += 512) {
        int row = p >> 8;
        int c2  = (p & 255) * 2;
        float t  = __ldg(&T[mbase + row]);
        float e0 = sincos_sel(__fmul_rn(t, g_invf[c2]), 0);
        float e1 = sincos_sel(__fmul_rn(t, g_invf[c2 + 1]), 1);
        __half2 h = __floats2half2_rn(e0, e1);
        int u = c2 >> 3;
        *(__half2*)(smem + A_OFF + u * A_PLANE + row * 16 + ((c2 & 7) << 1)) = h;
    }
    __syncthreads();    // A ready; the ONLY barrier. Warps free-run after.

    // ---- A ldmatrix lane geometry (unchanged from R13) ----
    const int arow0 = mw + ((lane >> 3) & 1) * 8 + (lane & 7);
    const int a_c8  = lane >> 4;
    const uint32_t a_base0 = sbase + A_OFF + (uint32_t)a_c8 * A_PLANE
                           + (uint32_t)arow0 * 16u;

    // B fragment source: per-(nb,g) 32KB block, chunk q -> 512B, lane -> 16B.
    const uint4* bsrc = (const uint4*)((const char*)g_W16 + (size_t)lane * 16u);
    // index in uint4 units: (blk*32768 + q*512)/16 = blk*2048 + q*32

    float acc[4][4][4];   // [m16-tile][n8-tile][quad] = 64 regs
    uint4 cur[4], nxt[4];

    // initial prefetch: nb=0, h=0 (q = 0..3)
    {
        size_t base = (size_t)g * 2048;
        #pragma unroll
        for (int t = 0; t < 4; t++)
            cur[t] = __ldg(bsrc + base + (size_t)t * 32);
    }

    #pragma unroll 1
    for (int nb = 0; nb < 4; nb++) {
        #pragma unroll
        for (int mt = 0; mt < 4; mt++)
            #pragma unroll
            for (int nt = 0; nt < 4; nt++) {
                acc[mt][nt][0] = 0.f; acc[mt][nt][1] = 0.f;
                acc[mt][nt][2] = 0.f; acc[mt][nt][3] = 0.f;
            }

        #pragma unroll 1
        for (int h = 0; h < 16; h++) {      // k32 steps over K=512
            // prefetch next k32 (possibly next nb chunk)
            int hn = h + 1, nbn = nb;
            if (hn == 16) { hn = 0; nbn = nb + 1; }
            if (nbn < 4) {
                size_t base = (size_t)(nbn * 8 + g) * 2048 + (size_t)hn * 128;
                #pragma unroll
                for (int t = 0; t < 4; t++)
                    nxt[t] = __ldg(bsrc + base + (size_t)t * 32);
            }

            // compute with cur: kkg = 2h, 2h+1
            #pragma unroll
            for (int m = 0; m < 2; m++) {
                uint32_t a[4][4];
                uint32_t a_kk = a_base0 + (uint32_t)((2 * h + m) * 2) * A_PLANE;
                #pragma unroll
                for (int mt = 0; mt < 4; mt++)
                    ldmat4(a_kk + (uint32_t)mt * 256u, a[mt]);
                #pragma unroll
                for (int j = 0; j < 2; j++) {
                    uint4 bv = cur[m * 2 + j];
                    #pragma unroll
                    for (int mt = 0; mt < 4; mt++) {
                        asm volatile(
                            "mma.sync.aligned.m16n8k16.row.col.f32.f16.f16.f32 "
                            "{%0,%1,%2,%3}, {%4,%5,%6,%7}, {%8,%9}, {%0,%1,%2,%3};"
                            : "+f"(acc[mt][2*j][0]), "+f"(acc[mt][2*j][1]),
                              "+f"(acc[mt][2*j][2]), "+f"(acc[mt][2*j][3])
                            : "r"(a[mt][0]), "r"(a[mt][1]), "r"(a[mt][2]), "r"(a[mt][3]),
                              "r"(bv.x), "r"(bv.y));
                        asm volatile(
                            "mma.sync.aligned.m16n8k16.row.col.f32.f16.f16.f32 "
                            "{%0,%1,%2,%3}, {%4,%5,%6,%7}, {%8,%9}, {%0,%1,%2,%3};"
                            : "+f"(acc[mt][2*j+1][0]), "+f"(acc[mt][2*j+1][1]),
                              "+f"(acc[mt][2*j+1][2]), "+f"(acc[mt][2*j+1][3])
                            : "r"(a[mt][0]), "r"(a[mt][1]), "r"(a[mt][2]), "r"(a[mt][3]),
                              "r"(bv.z), "r"(bv.w));
                    }
                }
            }

            #pragma unroll
            for (int t = 0; t < 4; t++) cur[t] = nxt[t];
        }

        // ---- Epilogue for finished 256-col chunk ----
        const int nchunk = nb * 256 + g * 32;
        #pragma unroll
        for (int mt = 0; mt < 4; mt++) {
            int row = mbase + mw + mt * 16 + (lane >> 2);
            #pragma unroll
            for (int nt = 0; nt < 4; nt++) {
                int col = nchunk + nt * 8 + (lane & 3) * 2;
                float2 bv = *(const float2*)(bias + col);
                float v0 = acc[mt][nt][0] + bv.x;
                float v1 = acc[mt][nt][1] + bv.y;
                float v2 = acc[mt][nt][2] + bv.x;
                float v3 = acc[mt][nt][3] + bv.y;
                v0 = v0 / (1.0f + __expf(-v0));
                v1 = v1 / (1.0f + __expf(-v1));
                v2 = v2 / (1.0f + __expf(-v2));
                v3 = v3 / (1.0f + __expf(-v3));
                *(float2*)(out + (size_t)row * 1024 + col)       = make_float2(v0, v1);
                *(float2*)(out + (size_t)(row + 8) * 1024 + col) = make_float2(v2, v3);
            }
        }
    }
}

// ---------------------------------------------------------------------------
extern "C" void kernel_launch(void* const* d_in, const int* in_sizes, int n_in,
                              void* d_out, int out_size) {
    const float* T = (const float*)d_in[0];
    const float* W = (const float*)d_in[1];
    const float* b = (const float*)d_in[2];
    float* out = (float*)d_out;

    prep_kernel<<<(TOUT * TDIM + 255) / 256, 256>>>(W);

    cudaFuncSetAttribute(temb_main, cudaFuncAttributeMaxDynamicSharedMemorySize, SMEM_TOTAL);
    temb_main<<<TBATCH / 128, 512, SMEM_TOTAL>>>(T, b, out);
}

// round 16
// speedup vs baseline: 1.0982x; 1.0526x over previous
#include <cuda_runtime.h>
#include <cuda_fp16.h>
#include <math.h>
#include <stdint.h>

#define TDIM 512
#define TOUT 1024
#define TBATCH 65536

// W in fp16, pre-transposed into per-(stage, group) 4KB blocks:
// block id b = (s*8 + g), s = c*8+kt (c: 256-row chunk, kt: 64-wide k-tile),
// g: 32-row N slice. Within block: elem (n',k=u*8+j) at (u*32+n')*8+j.
__device__ __half g_W16[TOUT * TDIM];
__device__ float  g_invf[TDIM];

__global__ void prep_kernel(const float* __restrict__ W) {
    int idx = blockIdx.x * blockDim.x + threadIdx.x;
    if (idx < TOUT * TDIM) {
        int b      = idx >> 11;            // 4KB block = 2048 elems
        int within = idx & 2047;
        int u  = within >> 8;              // k-unit 0..7
        int np = (within >> 3) & 31;       // local row 0..31
        int j  = within & 7;
        int g  = b & 7;
        int kt = (b >> 3) & 7;
        int c  = b >> 6;
        int row = c * 256 + g * 32 + np;
        int col = kt * 64 + u * 8 + j;
        g_W16[idx] = __float2half_rn(W[row * 512 + col]);
    }
    if (idx < TDIM) {
        float a  = (2.0f * (float)idx) / 512.0f;
        float xf = __fmul_rn(a, 9.210340371976184f);
        g_invf[idx] = (float)exp(-(double)xf);
    }
}

// Accurate sin/cos for x in [0, ~1024] rad via exact Cody-Waite reduction +
// MUFU.SIN on the reduced angle. odd=0 -> sin(x), odd=1 -> cos(x).
// Selection folded into the angle: sin(r + (q&1)*pi/2) == (q&1)?cos(r):sin(r).
__device__ __forceinline__ float sincos_sel(float x, int odd) {
    float j  = __fmaf_rn(x, 0.63661977236758134f, 12582912.0f);
    int   qi = __float_as_int(j);
    float jf = __fadd_rn(j, -12582912.0f);
    float r  = __fmaf_rn(jf, -1.57079601e+00f, x);
    r        = __fmaf_rn(jf, -3.13916473e-07f, r);
    r        = __fmaf_rn(jf, -5.39030253e-15f, r);
    int qq = qi + odd;
    float w = r + ((qq & 1) ? 1.57079632679f : 0.0f);   // FSEL + FADD
    float v = __sinf(w);                                 // MUFU.SIN, |w|<=2.36
    return (qq & 2) ? -v : v;
}

#define CP_ASYNC16(dst, src) \
    asm volatile("cp.async.cg.shared.global [%0], [%1], 16;" :: "r"(dst), "l"(src))
#define CP_COMMIT()  asm volatile("cp.async.commit_group;")
#define CP_WAIT1()   asm volatile("cp.async.wait_group 1;")
#define CP_WAIT0()   asm volatile("cp.async.wait_group 0;")
#define GBAR64(id)   asm volatile("bar.sync %0, 64;" :: "r"(id) : "memory")

// --------------------------- SMEM layout ------------------------------------
// A: 64 k-planes of [128 rows x 16B], plane stride 2080 (32B skew) = 133120 B
// B: 8 group-private rings, 3 stages x 4KB each (32 n x 64 k fp16) = 98304 B
#define A_OFF     0
#define A_PLANE   2080
#define B_OFF     133120
#define B_SLICE   4096
#define SMEM_TOTAL 231424

__device__ __forceinline__ void ldmat4(uint32_t addr, uint32_t* r) {
    asm volatile("ldmatrix.sync.aligned.m8n8.x4.shared.b16 {%0,%1,%2,%3}, [%4];"
                 : "=r"(r[0]), "=r"(r[1]), "=r"(r[2]), "=r"(r[3]) : "r"(addr));
}

// 512 threads, 16 warps = 2M x 8N; warp tile 64M x 32N; acc = 64 regs.
__global__ void __launch_bounds__(512, 1) temb_main(
    const float* __restrict__ T,
    const float* __restrict__ bias,
    float* __restrict__ out)
{
    extern __shared__ char smem[];
    const int tid = threadIdx.x;
    const int mbase = blockIdx.x * 128;
    uint32_t sbase;
    asm("{ .reg .u64 t; cvta.to.shared.u64 t, %1; cvt.u32.u64 %0, t; }"
        : "=r"(sbase) : "l"(smem));

    const int w      = tid >> 5;
    const int lane   = tid & 31;
    const int g      = w >> 1;          // N-slice group (0..7), 2 warps / 64 thr
    const int mw     = (w & 1) * 64;    // warp M offset (0 or 64)
    const int wg_tid = tid & 63;

    // Group-private ring; identity cp.async: 4KB slice, 4 x 16B per thread.
    const uint32_t ring = sbase + B_OFF + (uint32_t)(g * 3) * B_SLICE;
    uint32_t cp_off[4];
    #pragma unroll
    for (int i = 0; i < 4; i++) cp_off[i] = (uint32_t)(wg_tid * 16 + i * 1024);
    const char* wsrc = (const char*)g_W16;

    // ---- Prologue: start this group's pipeline for stages 0,1 ----
    #pragma unroll
    for (int s = 0; s < 2; s++) {
        const char* sb = wsrc + (size_t)(s * 8 + g) * 4096;
        uint32_t db = ring + (uint32_t)(s % 3) * B_SLICE;
        #pragma unroll
        for (int i = 0; i < 4; i++)
            CP_ASYNC16(db + cp_off[i], sb + cp_off[i]);
        CP_COMMIT();
    }

    // ---- Phase 1: embedding -> A smem (k-plane layout), overlaps cp.async ----
    for (int p = tid; p < 128 * 256; p += 512) {
        int row = p >> 8;
        int c2  = (p & 255) * 2;
        float t  = __ldg(&T[mbase + row]);
        float e0 = sincos_sel(__fmul_rn(t, g_invf[c2]), 0);
        float e1 = sincos_sel(__fmul_rn(t, g_invf[c2 + 1]), 1);
        __half2 h = __floats2half2_rn(e0, e1);
        int u = c2 >> 3;
        *(__half2*)(smem + A_OFF + u * A_PLANE + row * 16 + ((c2 & 7) << 1)) = h;
    }
    __syncthreads();    // A ready; ONLY CTA-wide barrier. Groups free-run after.

    // ---- ldmatrix lane geometry ----
    const int arow0 = mw + ((lane >> 3) & 1) * 8 + (lane & 7);
    const int a_c8  = lane >> 4;
    const int bn0   = (lane & 7) + ((lane >> 4) << 3);  // local n 0..15
    const int b_k8  = (lane >> 3) & 1;

    const uint32_t a_base0 = sbase + A_OFF + (uint32_t)a_c8 * A_PLANE
                           + (uint32_t)arow0 * 16u;
    const uint32_t b_lane  = (uint32_t)b_k8 * 512u + (uint32_t)bn0 * 16u;

    float acc[4][4][4];   // [m16-tile][n8-tile][quad] = 64 regs

    for (int s = 0; s < 32; s++) {
        const int kt = s & 7, nb = s >> 3, buf = s % 3;

        if (kt == 0) {
            #pragma unroll
            for (int mt = 0; mt < 4; mt++)
                #pragma unroll
                for (int nt = 0; nt < 4; nt++) {
                    acc[mt][nt][0] = 0.f; acc[mt][nt][1] = 0.f;
                    acc[mt][nt][2] = 0.f; acc[mt][nt][3] = 0.f;
                }
        }

        // Group-local: own cp.asyncs done (leave newest in flight), publish
        // slice within the 64-thread group only.
        if (s == 31) { CP_WAIT0(); } else { CP_WAIT1(); }
        GBAR64(g + 1);

        // issue stage s+2 into buffer (s+2)%3 (free: last read at iter s-1)
        if (s + 2 < 32) {
            int s2 = s + 2;
            const char* sb = wsrc + (size_t)(s2 * 8 + g) * 4096;
            uint32_t db = ring + (uint32_t)(s2 % 3) * B_SLICE;
            #pragma unroll
            for (int i = 0; i < 4; i++)
                CP_ASYNC16(db + cp_off[i], sb + cp_off[i]);
            CP_COMMIT();
        }

        // ---- MMA over this 64-wide k-tile ----
        const uint32_t a_kt = a_base0 + (uint32_t)(kt * 8) * A_PLANE;
        const uint32_t b_st = ring + (uint32_t)buf * B_SLICE + b_lane;
        #pragma unroll
        for (int kk = 0; kk < 4; kk++) {
            uint32_t a[4][4];
            const uint32_t a_kk = a_kt + (uint32_t)(kk * 2) * A_PLANE;
            #pragma unroll
            for (int mt = 0; mt < 4; mt++)
                ldmat4(a_kk + (uint32_t)mt * 256u, a[mt]);   // +16 rows * 16B
            const uint32_t b_kk = b_st + (uint32_t)kk * 1024u;
            #pragma unroll
            for (int j = 0; j < 2; j++) {
                uint32_t b[4];
                ldmat4(b_kk + (uint32_t)j * 256u, b);        // +16 local n rows
                #pragma unroll
                for (int mt = 0; mt < 4; mt++) {
                    asm volatile(
                        "mma.sync.aligned.m16n8k16.row.col.f32.f16.f16.f32 "
                        "{%0,%1,%2,%3}, {%4,%5,%6,%7}, {%8,%9}, {%0,%1,%2,%3};"
                        : "+f"(acc[mt][2*j][0]), "+f"(acc[mt][2*j][1]),
                          "+f"(acc[mt][2*j][2]), "+f"(acc[mt][2*j][3])
                        : "r"(a[mt][0]), "r"(a[mt][1]), "r"(a[mt][2]), "r"(a[mt][3]),
                          "r"(b[0]), "r"(b[1]));
                    asm volatile(
                        "mma.sync.aligned.m16n8k16.row.col.f32.f16.f16.f32 "
                        "{%0,%1,%2,%3}, {%4,%5,%6,%7}, {%8,%9}, {%0,%1,%2,%3};"
                        : "+f"(acc[mt][2*j+1][0]), "+f"(acc[mt][2*j+1][1]),
                          "+f"(acc[mt][2*j+1][2]), "+f"(acc[mt][2*j+1][3])
                        : "r"(a[mt][0]), "r"(a[mt][1]), "r"(a[mt][2]), "r"(a[mt][3]),
                          "r"(b[2]), "r"(b[3]));
                }
            }
        }

        // ---- Epilogue for finished 256-col chunk ----
        if (kt == 7) {
            const int nchunk = nb * 256 + g * 32;
            #pragma unroll
            for (int mt = 0; mt < 4; mt++) {
                int row = mbase + mw + mt * 16 + (lane >> 2);
                #pragma unroll
                for (int nt = 0; nt < 4; nt++) {
                    int col = nchunk + nt * 8 + (lane & 3) * 2;
                    float2 bv = *(const float2*)(bias + col);
                    float v0 = acc[mt][nt][0] + bv.x;
                    float v1 = acc[mt][nt][1] + bv.y;
                    float v2 = acc[mt][nt][2] + bv.x;
                    float v3 = acc[mt][nt][3] + bv.y;
                    v0 = v0 / (1.0f + __expf(-v0));
                    v1 = v1 / (1.0f + __expf(-v1));
                    v2 = v2 / (1.0f + __expf(-v2));
                    v3 = v3 / (1.0f + __expf(-v3));
                    *(float2*)(out + (size_t)row * 1024 + col)       = make_float2(v0, v1);
                    *(float2*)(out + (size_t)(row + 8) * 1024 + col) = make_float2(v2, v3);
                }
            }
        }
    }
}

// ---------------------------------------------------------------------------
extern "C" void kernel_launch(void* const* d_in, const int* in_sizes, int n_in,
                              void* d_out, int out_size) {
    const float* T = (const float*)d_in[0];
    const float* W = (const float*)d_in[1];
    const float* b = (const float*)d_in[2];
    float* out = (float*)d_out;

    prep_kernel<<<(TOUT * TDIM + 255) / 256, 256>>>(W);

    cudaFuncSetAttribute(temb_main, cudaFuncAttributeMaxDynamicSharedMemorySize, SMEM_TOTAL);
    temb_main<<<TBATCH / 128, 512, SMEM_TOTAL>>>(T, b, out);
}

// round 17
// speedup vs baseline: 1.1050x; 1.0062x over previous
#include <cuda_runtime.h>
#include <cuda_fp16.h>
#include <math.h>
#include <stdint.h>

#define TDIM 512
#define TOUT 1024
#define TBATCH 65536

// W in fp16, pre-transposed into per-(c, kt2, g) 2KB blocks:
// block b = (c*16 + kt2)*16 + g; c: 512-row W chunk, kt2: 32-wide k-tile,
// g: 32-row N slice. Within block: elem (n', k=u*8+j) at (u*32+n')*8+j.
__device__ __half g_W16[TOUT * TDIM];
__device__ float  g_invf[TDIM];

__global__ void prep_kernel(const float* __restrict__ W) {
    int idx = blockIdx.x * blockDim.x + threadIdx.x;
    if (idx < TOUT * TDIM) {
        int b      = idx >> 10;            // 2KB block = 1024 elems
        int within = idx & 1023;
        int u  = within >> 8;              // k-unit 0..3
        int np = (within >> 3) & 31;       // local row 0..31
        int j  = within & 7;
        int g   = b & 15;
        int kt2 = (b >> 4) & 15;
        int c   = b >> 8;
        int row = c * 512 + g * 32 + np;
        int col = kt2 * 32 + u * 8 + j;
        g_W16[idx] = __float2half_rn(W[row * 512 + col]);
    }
    if (idx < TDIM) {
        float a  = (2.0f * (float)idx) / 512.0f;
        float xf = __fmul_rn(a, 9.210340371976184f);
        g_invf[idx] = (float)exp(-(double)xf);
    }
}

// Accurate sin/cos for x in [0, ~1024] rad via exact Cody-Waite reduction +
// MUFU.SIN on the reduced angle (selection folded into the angle).
__device__ __forceinline__ float sincos_sel(float x, int odd) {
    float j  = __fmaf_rn(x, 0.63661977236758134f, 12582912.0f);
    int   qi = __float_as_int(j);
    float jf = __fadd_rn(j, -12582912.0f);
    float r  = __fmaf_rn(jf, -1.57079601e+00f, x);
    r        = __fmaf_rn(jf, -3.13916473e-07f, r);
    r        = __fmaf_rn(jf, -5.39030253e-15f, r);
    int qq = qi + odd;
    float w = r + ((qq & 1) ? 1.57079632679f : 0.0f);
    float v = __sinf(w);
    return (qq & 2) ? -v : v;
}

#define CP_ASYNC16(dst, src) \
    asm volatile("cp.async.cg.shared.global [%0], [%1], 16;" :: "r"(dst), "l"(src))
#define CP_COMMIT()  asm volatile("cp.async.commit_group;")
#define CP_WAIT1()   asm volatile("cp.async.wait_group 1;")
#define CP_WAIT0()   asm volatile("cp.async.wait_group 0;")

// --------------------------- SMEM layout ------------------------------------
// A: 64 k-planes of [64 rows x 16B], plane stride 1056 (32B skew) = 67584 B
// B: 16 warp-private rings, 3 stages x 2KB each (32 n x 32 k fp16) = 98304 B
#define A_OFF     0
#define A_PLANE   1056
#define B_OFF     67584
#define B_SLICE   2048
#define SMEM_TOTAL 165888

__device__ __forceinline__ void ldmat4(uint32_t addr, uint32_t* r) {
    asm volatile("ldmatrix.sync.aligned.m8n8.x4.shared.b16 {%0,%1,%2,%3}, [%4];"
                 : "=r"(r[0]), "=r"(r[1]), "=r"(r[2]), "=r"(r[3]) : "r"(addr));
}

// 512 threads, 16 warps; CTA tile M=64 x N=1024; warp tile 64M x 32N.
// Warp w owns N slice w*32 within each 512-col chunk; mainloop barrier-free.
__global__ void __launch_bounds__(512, 1) temb_main(
    const float* __restrict__ T,
    const float* __restrict__ bias,
    float* __restrict__ out)
{
    extern __shared__ char smem[];
    const int tid = threadIdx.x;
    const int mbase = blockIdx.x * 64;
    uint32_t sbase;
    asm("{ .reg .u64 t; cvta.to.shared.u64 t, %1; cvt.u32.u64 %0, t; }"
        : "=r"(sbase) : "l"(smem));

    const int w    = tid >> 5;
    const int lane = tid & 31;

    // Warp-private ring; identity cp.async: 2KB slice, 4 x 16B per lane.
    const uint32_t ring = sbase + B_OFF + (uint32_t)(w * 3) * B_SLICE;
    uint32_t cp_off[4];
    #pragma unroll
    for (int i = 0; i < 4; i++) cp_off[i] = (uint32_t)((lane + i * 32) * 16);
    const char* wsrc = (const char*)g_W16;

    // ---- Prologue: start this warp's pipeline for stages 0,1 ----
    #pragma unroll
    for (int s = 0; s < 2; s++) {
        const char* sb = wsrc + (size_t)(s * 16 + w) * 2048;
        uint32_t db = ring + (uint32_t)(s % 3) * B_SLICE;
        #pragma unroll
        for (int i = 0; i < 4; i++)
            CP_ASYNC16(db + cp_off[i], sb + cp_off[i]);
        CP_COMMIT();
    }

    // ---- Phase 1: embedding -> A smem (k-plane layout), overlaps cp.async ----
    for (int p = tid; p < 64 * 256; p += 512) {
        int row = p >> 8;
        int c2  = (p & 255) * 2;
        float t  = __ldg(&T[mbase + row]);
        float e0 = sincos_sel(__fmul_rn(t, g_invf[c2]), 0);
        float e1 = sincos_sel(__fmul_rn(t, g_invf[c2 + 1]), 1);
        __half2 h = __floats2half2_rn(e0, e1);
        int u = c2 >> 3;
        *(__half2*)(smem + A_OFF + u * A_PLANE + row * 16 + ((c2 & 7) << 1)) = h;
    }
    __syncthreads();    // A ready; the ONLY CTA barrier. Warps free-run after.

    // ---- ldmatrix lane geometry ----
    const int arow0 = ((lane >> 3) & 1) * 8 + (lane & 7);
    const int a_c8  = lane >> 4;                        // A k-unit select (0/1)
    const int bn0   = (lane & 7) + ((lane >> 4) << 3);  // local n 0..15
    const int b_k8  = (lane >> 3) & 1;                  // B k-unit select (0/1)

    const uint32_t a_base0 = sbase + A_OFF + (uint32_t)a_c8 * A_PLANE
                           + (uint32_t)arow0 * 16u;
    const uint32_t b_lane  = (uint32_t)b_k8 * 512u + (uint32_t)bn0 * 16u;

    float acc[4][4][4];   // [m16-tile][n8-tile][quad] = 64 regs

    for (int s = 0; s < 32; s++) {
        const int t16 = s & 15, nb = s >> 4, buf = s % 3;

        if (t16 == 0) {
            #pragma unroll
            for (int mt = 0; mt < 4; mt++)
                #pragma unroll
                for (int nt = 0; nt < 4; nt++) {
                    acc[mt][nt][0] = 0.f; acc[mt][nt][1] = 0.f;
                    acc[mt][nt][2] = 0.f; acc[mt][nt][3] = 0.f;
                }
        }

        // Warp-local: own cp.asyncs done (leave newest in flight); syncwarp
        // publishes lanes' slices to each other. No CTA/named barriers.
        if (s == 31) { CP_WAIT0(); } else { CP_WAIT1(); }
        __syncwarp();

        // issue stage s+2 into buffer (s+2)%3 (free: last read at iter s-1)
        if (s + 2 < 32) {
            int s2 = s + 2;
            const char* sb = wsrc + (size_t)(s2 * 16 + w) * 2048;
            uint32_t db = ring + (uint32_t)(s2 % 3) * B_SLICE;
            #pragma unroll
            for (int i = 0; i < 4; i++)
                CP_ASYNC16(db + cp_off[i], sb + cp_off[i]);
            CP_COMMIT();
        }

        // ---- MMA over this 32-wide k-tile ----
        const uint32_t b_st = ring + (uint32_t)buf * B_SLICE + b_lane;
        #pragma unroll
        for (int kk = 0; kk < 2; kk++) {
            const int kkg = t16 * 2 + kk;           // global k16 step
            uint32_t a[4][4];
            const uint32_t a_kk = a_base0 + (uint32_t)(kkg * 2) * A_PLANE;
            #pragma unroll
            for (int mt = 0; mt < 4; mt++)
                ldmat4(a_kk + (uint32_t)mt * 256u, a[mt]);   // +16 rows * 16B
            const uint32_t b_kk = b_st + (uint32_t)kk * 1024u;
            #pragma unroll
            for (int j = 0; j < 2; j++) {
                uint32_t b[4];
                ldmat4(b_kk + (uint32_t)j * 256u, b);        // +16 local n rows
                #pragma unroll
                for (int mt = 0; mt < 4; mt++) {
                    asm volatile(
                        "mma.sync.aligned.m16n8k16.row.col.f32.f16.f16.f32 "
                        "{%0,%1,%2,%3}, {%4,%5,%6,%7}, {%8,%9}, {%0,%1,%2,%3};"
                        : "+f"(acc[mt][2*j][0]), "+f"(acc[mt][2*j][1]),
                          "+f"(acc[mt][2*j][2]), "+f"(acc[mt][2*j][3])
                        : "r"(a[mt][0]), "r"(a[mt][1]), "r"(a[mt][2]), "r"(a[mt][3]),
                          "r"(b[0]), "r"(b[1]));
                    asm volatile(
                        "mma.sync.aligned.m16n8k16.row.col.f32.f16.f16.f32 "
                        "{%0,%1,%2,%3}, {%4,%5,%6,%7}, {%8,%9}, {%0,%1,%2,%3};"
                        : "+f"(acc[mt][2*j+1][0]), "+f"(acc[mt][2*j+1][1]),
                          "+f"(acc[mt][2*j+1][2]), "+f"(acc[mt][2*j+1][3])
                        : "r"(a[mt][0]), "r"(a[mt][1]), "r"(a[mt][2]), "r"(a[mt][3]),
                          "r"(b[2]), "r"(b[3]));
                }
            }
        }

        // ---- Epilogue for finished 512-col chunk ----
        if (t16 == 15) {
            const int nchunk = nb * 512 + w * 32;
            #pragma unroll
            for (int mt = 0; mt < 4; mt++) {
                int row = mbase + mt * 16 + (lane >> 2);
                #pragma unroll
                for (int nt = 0; nt < 4; nt++) {
                    int col = nchunk + nt * 8 + (lane & 3) * 2;
                    float2 bv = *(const float2*)(bias + col);
                    float v0 = acc[mt][nt][0] + bv.x;
                    float v1 = acc[mt][nt][1] + bv.y;
                    float v2 = acc[mt][nt][2] + bv.x;
                    float v3 = acc[mt][nt][3] + bv.y;
                    v0 = v0 / (1.0f + __expf(-v0));
                    v1 = v1 / (1.0f + __expf(-v1));
                    v2 = v2 / (1.0f + __expf(-v2));
                    v3 = v3 / (1.0f + __expf(-v3));
                    *(float2*)(out + (size_t)row * 1024 + col)       = make_float2(v0, v1);
                    *(float2*)(out + (size_t)(row + 8) * 1024 + col) = make_float2(v2, v3);
                }
            }
        }
    }
}

// ---------------------------------------------------------------------------
extern "C" void kernel_launch(void* const* d_in, const int* in_sizes, int n_in,
                              void* d_out, int out_size) {
    const float* T = (const float*)d_in[0];
    const float* W = (const float*)d_in[1];
    const float* b = (const float*)d_in[2];
    float* out = (float*)d_out;

    prep_kernel<<<(TOUT * TDIM + 255) / 256, 256>>>(W);

    cudaFuncSetAttribute(temb_main, cudaFuncAttributeMaxDynamicSharedMemorySize, SMEM_TOTAL);
    temb_main<<<TBATCH / 64, 512, SMEM_TOTAL>>>(T, b, out);
}